// round 7
// baseline (speedup 1.0000x reference)
#include <cuda_runtime.h>
#include <cuda_bf16.h>
#include <math.h>
#include <stdint.h>

// Shapes (fixed)
#define BATCH 8
#define CDIM 512
#define HWDIM 4096
#define CPG 16
#define EPSV 1e-6f

// GEMM tiling: 128x256 CTA tile, 256 threads (8 warps, 2x4), warp tile 64x64
#define TM 128
#define TN 256
#define BK 64
#define A_BYTES (TM * 128)              // 16KB
#define B_BYTES (TN * 128)              // 32KB
#define STG_BYTES (A_BYTES + B_BYTES)   // 48KB
#define NSTAGE 4
#define SMEM_DYN (NSTAGE * STG_BYTES)   // 192KB

typedef __nv_bfloat16 bf16;
typedef __nv_bfloat162 bf162;

// ---------------- scratch (device globals) ---------------------------------
__device__ bf16  g_xnb [(size_t)BATCH * HWDIM * CDIM];   // 32MB  GN out [B,N,C]
__device__ bf16  g_qb  [(size_t)BATCH * HWDIM * CDIM];   // 32MB
__device__ bf16  g_kb  [(size_t)BATCH * HWDIM * CDIM];   // 32MB
__device__ bf16  g_vb  [(size_t)BATCH * HWDIM * CDIM];   // 32MB
__device__ bf16  g_vtb [(size_t)BATCH * HWDIM * CDIM];   // 32MB  V^T [B,C,N]
__device__ bf16  g_pb  [(size_t)BATCH * HWDIM * HWDIM];  // 256MB softmax(P) bf16
__device__ bf16  g_attnb[(size_t)BATCH * HWDIM * CDIM];  // 32MB  P@V out
__device__ bf16  g_wb  [4 * CDIM * CDIM];                // 2MB   bf16 weights
__device__ float g_s   [(size_t)BATCH * HWDIM * HWDIM];  // 512MB scores f32

// ---------------- PTX helpers ----------------------------------------------
__device__ __forceinline__ uint32_t smem_u32(const void* p) {
    uint32_t a;
    asm("{ .reg .u64 t; cvta.to.shared.u64 t, %1; cvt.u32.u64 %0, t; }"
        : "=r"(a) : "l"(p));
    return a;
}

__device__ __forceinline__ void ldsm4(uint32_t* r, uint32_t addr) {
    asm volatile("ldmatrix.sync.aligned.m8n8.x4.shared.b16 {%0,%1,%2,%3}, [%4];"
                 : "=r"(r[0]), "=r"(r[1]), "=r"(r[2]), "=r"(r[3]) : "r"(addr));
}

__device__ __forceinline__ void mma_bf16(float* c, const uint32_t* a,
                                         uint32_t b0, uint32_t b1) {
    asm volatile(
        "mma.sync.aligned.m16n8k16.row.col.f32.bf16.bf16.f32 "
        "{%0,%1,%2,%3}, {%4,%5,%6,%7}, {%8,%9}, {%0,%1,%2,%3};"
        : "+f"(c[0]), "+f"(c[1]), "+f"(c[2]), "+f"(c[3])
        : "r"(a[0]), "r"(a[1]), "r"(a[2]), "r"(a[3]), "r"(b0), "r"(b1));
}

__device__ __forceinline__ void cp16(uint32_t dst, const void* src) {
    asm volatile("cp.async.cg.shared.global [%0], [%1], 16;" :: "r"(dst), "l"(src));
}
#define CP_COMMIT() asm volatile("cp.async.commit_group;" ::: "memory")
#define CP_WAIT2()  asm volatile("cp.async.wait_group 2;" ::: "memory")

// ---------------- bf16 GEMM NT: C = alpha * A @ B^T (+ bias) ----------------
// A: [M,K] lda, B: [N,K] ldb bf16 K-major.
// mode 0: f32 C row-major   mode 1: bf16 C row-major
// mode 2: fused residual + transpose: out[(m>>12)*512 + n][m&4095] = acc + x[...]
__global__ __launch_bounds__(256) void gemm_bf16(const bf16* __restrict__ A,
                                                 const bf16* __restrict__ B,
                                                 const float* __restrict__ bias,
                                                 void* __restrict__ Cv,
                                                 const float* __restrict__ xres,
                                                 int K, int lda, int ldb, int ldc,
                                                 float alpha, int mode,
                                                 size_t sA, size_t sB, size_t sC) {
    extern __shared__ char dsm[];
    uint32_t smem_base = smem_u32(dsm);

    A += (size_t)blockIdx.z * sA;
    B += (size_t)blockIdx.z * sB;
    int bm = blockIdx.y * TM, bn = blockIdx.x * TN;
    int tid = threadIdx.x, wid = tid >> 5, lane = tid & 31;
    int wm = (wid & 1) * 64;      // warp M offset (2 x 64 = 128)
    int wn = (wid >> 1) * 64;     // warp N offset (4 x 64 = 256)

    // cooperative load, A: 2 threads/row x 128 rows, 4 granules each
    int larow = tid >> 1;                 // 0..127
    int lag = (tid & 1) * 4;              // granule base 0 or 4
    const bf16* ag = A + (size_t)(bm + larow) * lda + lag * 8;
    int larx = larow & 7;
    uint32_t sAoff[4];
    #pragma unroll
    for (int j = 0; j < 4; j++)
        sAoff[j] = (uint32_t)larow * 128 + (uint32_t)(((lag + j) ^ larx) << 4);

    // cooperative load, B: 1 thread/row x 256 rows, 8 granules each
    int lbrow = tid;                      // 0..255
    const bf16* bg = B + (size_t)(bn + lbrow) * ldb;
    int lbrx = lbrow & 7;
    uint32_t sBoff[8];
    #pragma unroll
    for (int j = 0; j < 8; j++)
        sBoff[j] = A_BYTES + (uint32_t)lbrow * 128 + (uint32_t)((j ^ lbrx) << 4);

    // ldmatrix lane addressing (tile-relative byte offsets)
    int arl = (lane & 7) + ((lane >> 3) & 1) * 8;
    int ahi = lane >> 4;
    uint32_t a_rowoff[4]; int a_rx[4];
    #pragma unroll
    for (int mf = 0; mf < 4; mf++) {
        int row = wm + mf * 16 + arl;
        a_rowoff[mf] = (uint32_t)row * 128;
        a_rx[mf] = row & 7;
    }
    int brl = (lane & 7) + ((lane >> 4) & 1) * 8;
    int bhi = (lane >> 3) & 1;
    uint32_t b_rowoff[4]; int b_rx[4];
    #pragma unroll
    for (int ng = 0; ng < 4; ng++) {
        int row = wn + ng * 16 + brl;
        b_rowoff[ng] = A_BYTES + (uint32_t)row * 128;
        b_rx[ng] = row & 7;
    }

    const int NC = K / BK;

    // prologue: stages 0,1,2
    #pragma unroll
    for (int c = 0; c < 3; c++) {
        uint32_t st = smem_base + c * STG_BYTES;
        const bf16* a0 = ag + c * BK;
        const bf16* b0 = bg + c * BK;
        #pragma unroll
        for (int j = 0; j < 4; j++) cp16(st + sAoff[j], a0 + j * 8);
        #pragma unroll
        for (int j = 0; j < 8; j++) cp16(st + sBoff[j], b0 + j * 8);
        CP_COMMIT();
    }

    float acc[4][8][4];
    #pragma unroll
    for (int i = 0; i < 4; i++)
        #pragma unroll
        for (int j = 0; j < 8; j++)
            #pragma unroll
            for (int r = 0; r < 4; r++) acc[i][j][r] = 0.f;

    for (int c = 0; c < NC; c++) {
        int buf = c % NSTAGE;
        CP_WAIT2();
        __syncthreads();
        // prefetch stage c+3 (safe: all warps passed barrier => iter c-1 reads done)
        if (c + 3 < NC) {
            uint32_t st = smem_base + ((c + 3) % NSTAGE) * STG_BYTES;
            const bf16* a0 = ag + (c + 3) * BK;
            const bf16* b0 = bg + (c + 3) * BK;
            #pragma unroll
            for (int j = 0; j < 4; j++) cp16(st + sAoff[j], a0 + j * 8);
            #pragma unroll
            for (int j = 0; j < 8; j++) cp16(st + sBoff[j], b0 + j * 8);
        }
        CP_COMMIT();

        uint32_t base = smem_base + buf * STG_BYTES;
        #pragma unroll
        for (int kf = 0; kf < 4; kf++) {
            uint32_t a[4][4], b[4][4];
            #pragma unroll
            for (int mf = 0; mf < 4; mf++)
                ldsm4(a[mf], base + a_rowoff[mf] +
                      (uint32_t)(((((kf << 1) | ahi)) ^ a_rx[mf]) << 4));
            #pragma unroll
            for (int ng = 0; ng < 4; ng++)
                ldsm4(b[ng], base + b_rowoff[ng] +
                      (uint32_t)(((((kf << 1) | bhi)) ^ b_rx[ng]) << 4));
            #pragma unroll
            for (int mf = 0; mf < 4; mf++)
                #pragma unroll
                for (int ng = 0; ng < 4; ng++) {
                    mma_bf16(acc[mf][ng * 2 + 0], a[mf], b[ng][0], b[ng][1]);
                    mma_bf16(acc[mf][ng * 2 + 1], a[mf], b[ng][2], b[ng][3]);
                }
        }
    }
    __syncthreads();

    // epilogue
    int r4 = lane >> 2, c2 = (lane & 3) * 2;
    #pragma unroll
    for (int mf = 0; mf < 4; mf++) {
        int m0 = bm + wm + mf * 16 + r4;
        #pragma unroll
        for (int nf = 0; nf < 8; nf++) {
            int n0 = bn + wn + (nf >> 1) * 16 + (nf & 1) * 8 + c2;
            float bx = 0.f, by = 0.f;
            if (bias) { bx = bias[n0]; by = bias[n0 + 1]; }
            float* ac = acc[mf][nf];
            float x0 = ac[0] * alpha + bx, y0 = ac[1] * alpha + by;
            float x1 = ac[2] * alpha + bx, y1 = ac[3] * alpha + by;
            if (mode == 1) {
                bf16* C = (bf16*)Cv + blockIdx.z * sC;
                bf162 h0 = __floats2bfloat162_rn(x0, y0);
                bf162 h1 = __floats2bfloat162_rn(x1, y1);
                *(bf162*)(C + (size_t)m0 * ldc + n0) = h0;
                *(bf162*)(C + (size_t)(m0 + 8) * ldc + n0) = h1;
            } else if (mode == 0) {
                float* C = (float*)Cv + blockIdx.z * sC;
                *(float2*)(C + (size_t)m0 * ldc + n0) = make_float2(x0, y0);
                *(float2*)(C + (size_t)(m0 + 8) * ldc + n0) = make_float2(x1, y1);
            } else {
                // fused residual + transpose to [B, C, H, W]
                float* C = (float*)Cv;
                int m1 = m0 + 8;
                size_t i00 = (((size_t)(m0 >> 12) * CDIM) + n0) * HWDIM + (m0 & 4095);
                size_t i01 = (((size_t)(m0 >> 12) * CDIM) + n0 + 1) * HWDIM + (m0 & 4095);
                size_t i10 = (((size_t)(m1 >> 12) * CDIM) + n0) * HWDIM + (m1 & 4095);
                size_t i11 = (((size_t)(m1 >> 12) * CDIM) + n0 + 1) * HWDIM + (m1 & 4095);
                C[i00] = x0 + xres[i00];
                C[i01] = y0 + xres[i01];
                C[i10] = x1 + xres[i10];
                C[i11] = y1 + xres[i11];
            }
        }
    }
}

// ---------------- weight f32 -> bf16 (all 4 in one launch) ------------------
__global__ __launch_bounds__(256) void convert_w(const float* __restrict__ W0,
                                                 const float* __restrict__ W1,
                                                 const float* __restrict__ W2,
                                                 const float* __restrict__ W3,
                                                 bf16* __restrict__ out) {
    int i = blockIdx.x * 256 + threadIdx.x;
    const int WN = CDIM * CDIM;
    int sel = i / WN, r = i % WN;
    const float* W = (sel == 0) ? W0 : (sel == 1) ? W1 : (sel == 2) ? W2 : W3;
    out[i] = __float2bfloat16(W[r]);
}

// ---------------- GroupNorm -> bf16 [B,N,C] --------------------------------
__global__ __launch_bounds__(256) void gn_kernel(const float* __restrict__ x,
                                                 const float* __restrict__ gamma,
                                                 const float* __restrict__ beta,
                                                 bf16* __restrict__ xn) {
    int b = blockIdx.x >> 5;
    int g = blockIdx.x & 31;
    const float* xp = x + ((size_t)b * CDIM + (size_t)g * CPG) * HWDIM;
    const int NEL = CPG * HWDIM;

    float s = 0.f, s2 = 0.f;
    for (int i = threadIdx.x; i < NEL; i += 256) {
        float v = xp[i];
        s += v; s2 += v * v;
    }
    __shared__ float rs[256], rs2[256];
    rs[threadIdx.x] = s; rs2[threadIdx.x] = s2;
    __syncthreads();
    for (int st = 128; st > 0; st >>= 1) {
        if (threadIdx.x < st) { rs[threadIdx.x] += rs[threadIdx.x + st];
                                rs2[threadIdx.x] += rs2[threadIdx.x + st]; }
        __syncthreads();
    }
    float mean = rs[0] * (1.f / NEL);
    float var  = rs2[0] * (1.f / NEL) - mean * mean;
    float rstd = rsqrtf(var + EPSV);

    for (int i = threadIdx.x; i < NEL; i += 256) {
        int c  = i & (CPG - 1);
        int hw = i >> 4;
        int cg = g * CPG + c;
        float v = xp[(size_t)c * HWDIM + hw];
        xn[((size_t)b * HWDIM + hw) * CDIM + cg] =
            __float2bfloat16((v - mean) * rstd * gamma[cg] + beta[cg]);
    }
}

// ---------------- Transpose V (bf16): [B,N,C] -> [B,C,N] --------------------
__global__ __launch_bounds__(256) void transpose_vt(const bf16* __restrict__ V,
                                                    bf16* __restrict__ Vt) {
    __shared__ bf16 t[32][34];
    int b  = blockIdx.z;
    int n0 = blockIdx.x * 32;
    int c0 = blockIdx.y * 32;
    int tx = threadIdx.x & 31, ty = threadIdx.x >> 5;
    const size_t str = (size_t)HWDIM * CDIM;
    #pragma unroll
    for (int i = 0; i < 4; i++)
        t[ty + i * 8][tx] = V[b * str + (size_t)(n0 + ty + i * 8) * CDIM + c0 + tx];
    __syncthreads();
    #pragma unroll
    for (int i = 0; i < 4; i++)
        Vt[b * str + (size_t)(c0 + ty + i * 8) * HWDIM + n0 + tx] = t[tx][ty + i * 8];
}

// ---------------- Softmax: f32 S row -> bf16 P row --------------------------
__global__ __launch_bounds__(256) void softmax_kernel(const float* __restrict__ S,
                                                      bf16* __restrict__ P) {
    __shared__ float row[HWDIM];
    __shared__ float red[256];
    const float* g = S + (size_t)blockIdx.x * HWDIM;
    bf16* p = P + (size_t)blockIdx.x * HWDIM;
    int tid = threadIdx.x;

    float m = -1e30f;
    #pragma unroll
    for (int i = 0; i < 4; i++) {
        float4 v = *(const float4*)(g + (tid + i * 256) * 4);
        *(float4*)(row + (tid + i * 256) * 4) = v;
        m = fmaxf(m, fmaxf(fmaxf(v.x, v.y), fmaxf(v.z, v.w)));
    }
    red[tid] = m; __syncthreads();
    for (int st = 128; st > 0; st >>= 1) {
        if (tid < st) red[tid] = fmaxf(red[tid], red[tid + st]);
        __syncthreads();
    }
    m = red[0];
    __syncthreads();

    float sum = 0.f;
    #pragma unroll
    for (int i = 0; i < 4; i++) {
        float4 v = *(float4*)(row + (tid + i * 256) * 4);
        v.x = __expf(v.x - m); v.y = __expf(v.y - m);
        v.z = __expf(v.z - m); v.w = __expf(v.w - m);
        *(float4*)(row + (tid + i * 256) * 4) = v;
        sum += v.x + v.y + v.z + v.w;
    }
    red[tid] = sum; __syncthreads();
    for (int st = 128; st > 0; st >>= 1) {
        if (tid < st) red[tid] += red[tid + st];
        __syncthreads();
    }
    float inv = 1.f / red[0];
    #pragma unroll
    for (int i = 0; i < 4; i++) {
        int i4 = (tid + i * 256) * 4;
        float4 v = *(float4*)(row + i4);
        bf162 h0 = __floats2bfloat162_rn(v.x * inv, v.y * inv);
        bf162 h1 = __floats2bfloat162_rn(v.z * inv, v.w * inv);
        uint2 pk;
        pk.x = *(uint32_t*)&h0;
        pk.y = *(uint32_t*)&h1;
        *(uint2*)(p + i4) = pk;
    }
}

// ---------------- launch ----------------------------------------------------
extern "C" void kernel_launch(void* const* d_in, const int* in_sizes, int n_in,
                              void* d_out, int out_size) {
    const float* x     = (const float*)d_in[0];
    const float* gamma = (const float*)d_in[1];
    const float* beta  = (const float*)d_in[2];
    const float* Wq    = (const float*)d_in[3];
    const float* bq    = (const float*)d_in[4];
    const float* Wk    = (const float*)d_in[5];
    const float* bk    = (const float*)d_in[6];
    const float* Wv    = (const float*)d_in[7];
    const float* bv    = (const float*)d_in[8];
    const float* Wo    = (const float*)d_in[9];
    float* out = (float*)d_out;

    bf16 *xnb, *qb, *kb, *vb, *vtb, *pb, *attnb, *wb;
    float *s;
    cudaGetSymbolAddress((void**)&xnb,   g_xnb);
    cudaGetSymbolAddress((void**)&qb,    g_qb);
    cudaGetSymbolAddress((void**)&kb,    g_kb);
    cudaGetSymbolAddress((void**)&vb,    g_vb);
    cudaGetSymbolAddress((void**)&vtb,   g_vtb);
    cudaGetSymbolAddress((void**)&pb,    g_pb);
    cudaGetSymbolAddress((void**)&attnb, g_attnb);
    cudaGetSymbolAddress((void**)&wb,    g_wb);
    cudaGetSymbolAddress((void**)&s,     g_s);

    static bool attr_set = false;
    if (!attr_set) {
        cudaFuncSetAttribute(gemm_bf16, cudaFuncAttributeMaxDynamicSharedMemorySize, SMEM_DYN);
        attr_set = true;
    }

    const int M_all = BATCH * HWDIM;
    const size_t strQ = (size_t)HWDIM * CDIM;
    const size_t strS = (size_t)HWDIM * HWDIM;
    const int WN = CDIM * CDIM;
    const float inv_sqrt_c = 0.044194173824159216f;

    bf16* wqb = wb;
    bf16* wkb = wb + WN;
    bf16* wvb = wb + 2 * WN;
    bf16* wob = wb + 3 * WN;

    // 0. weights -> bf16 (one launch)
    convert_w<<<4 * WN / 256, 256>>>(Wq, Wk, Wv, Wo, wb);

    // 1. GroupNorm -> bf16 [B,N,C]
    gn_kernel<<<BATCH * 32, 256>>>(x, gamma, beta, xnb);

    // 2. Q/K/V projections (bf16 out)
    dim3 gproj(CDIM / TN, M_all / TM, 1);
    gemm_bf16<<<gproj, 256, SMEM_DYN>>>(xnb, wqb, bq, qb, nullptr,
                                        CDIM, CDIM, CDIM, CDIM, 1.f, 1, 0, 0, 0);
    gemm_bf16<<<gproj, 256, SMEM_DYN>>>(xnb, wkb, bk, kb, nullptr,
                                        CDIM, CDIM, CDIM, CDIM, 1.f, 1, 0, 0, 0);
    gemm_bf16<<<gproj, 256, SMEM_DYN>>>(xnb, wvb, bv, vb, nullptr,
                                        CDIM, CDIM, CDIM, CDIM, 1.f, 1, 0, 0, 0);

    // 3. V^T
    dim3 gtr(HWDIM / 32, CDIM / 32, BATCH);
    transpose_vt<<<gtr, 256>>>(vb, vtb);

    // 4. S = (Q @ K^T) / sqrt(C)  (f32 out)
    dim3 gs(HWDIM / TN, HWDIM / TM, BATCH);
    gemm_bf16<<<gs, 256, SMEM_DYN>>>(qb, kb, nullptr, s, nullptr,
                                     CDIM, CDIM, CDIM, HWDIM,
                                     inv_sqrt_c, 0, strQ, strQ, strS);

    // 5. softmax -> bf16 P
    softmax_kernel<<<M_all, 256>>>(s, pb);

    // 6. A = P @ Vt^T  (bf16 out)
    dim3 gpv(CDIM / TN, HWDIM / TM, BATCH);
    gemm_bf16<<<gpv, 256, SMEM_DYN>>>(pb, vtb, nullptr, attnb, nullptr,
                                      HWDIM, HWDIM, HWDIM, CDIM,
                                      1.f, 1, strS, strQ, strQ);

    // 7. O = A @ Wo^T fused with residual + transpose to [B,C,H,W]
    gemm_bf16<<<gproj, 256, SMEM_DYN>>>(attnb, wob, nullptr, out, x,
                                        CDIM, CDIM, CDIM, CDIM, 1.f, 2, 0, 0, 0);
}

// round 8
// speedup vs baseline: 1.3635x; 1.3635x over previous
#include <cuda_runtime.h>
#include <cuda_bf16.h>
#include <math.h>
#include <stdint.h>

// Shapes (fixed)
#define BATCH 8
#define CDIM 512
#define HWDIM 4096
#define CPG 16
#define EPSV 1e-6f

// GEMM tiling: 128x128 CTA tile, BK=64 bf16 (128B rows), 3-stage cp.async
#define TM 128
#define TN 128
#define BK 64
#define TILE_BYTES (TM * 128)           // 16KB per operand stage
#define STG_BYTES (2 * TILE_BYTES)      // 32KB
#define NSTAGE 3
#define SMEM_DYN (NSTAGE * STG_BYTES)   // 96KB

typedef __nv_bfloat16 bf16;
typedef __nv_bfloat162 bf162;

// ---------------- scratch (device globals) ---------------------------------
__device__ bf16  g_xnb [(size_t)BATCH * HWDIM * CDIM];       // 32MB GN out [B,N,C]
__device__ bf16  g_qkv [(size_t)3 * BATCH * HWDIM * CDIM];   // 96MB Q,K,V
__device__ bf16  g_vtb [(size_t)BATCH * HWDIM * CDIM];       // 32MB V^T [B,C,N]
__device__ bf16  g_sb  [(size_t)BATCH * HWDIM * HWDIM];      // 256MB scores bf16
__device__ bf16  g_pb  [(size_t)BATCH * HWDIM * HWDIM];      // 256MB softmax(P)
__device__ bf16  g_attnb[(size_t)BATCH * HWDIM * CDIM];      // 32MB P@V out
__device__ bf16  g_wb  [4 * CDIM * CDIM];                    // 2MB bf16 weights
__device__ float g_biasp[3 * CDIM];                          // packed biases

// ---------------- PTX helpers ----------------------------------------------
__device__ __forceinline__ uint32_t smem_u32(const void* p) {
    uint32_t a;
    asm("{ .reg .u64 t; cvta.to.shared.u64 t, %1; cvt.u32.u64 %0, t; }"
        : "=r"(a) : "l"(p));
    return a;
}

__device__ __forceinline__ void ldsm4(uint32_t* r, uint32_t addr) {
    asm volatile("ldmatrix.sync.aligned.m8n8.x4.shared.b16 {%0,%1,%2,%3}, [%4];"
                 : "=r"(r[0]), "=r"(r[1]), "=r"(r[2]), "=r"(r[3]) : "r"(addr));
}

__device__ __forceinline__ void mma_bf16(float* c, const uint32_t* a,
                                         uint32_t b0, uint32_t b1) {
    asm volatile(
        "mma.sync.aligned.m16n8k16.row.col.f32.bf16.bf16.f32 "
        "{%0,%1,%2,%3}, {%4,%5,%6,%7}, {%8,%9}, {%0,%1,%2,%3};"
        : "+f"(c[0]), "+f"(c[1]), "+f"(c[2]), "+f"(c[3])
        : "r"(a[0]), "r"(a[1]), "r"(a[2]), "r"(a[3]), "r"(b0), "r"(b1));
}

__device__ __forceinline__ void cp16(uint32_t dst, const void* src) {
    asm volatile("cp.async.cg.shared.global [%0], [%1], 16;" :: "r"(dst), "l"(src));
}
#define CP_COMMIT() asm volatile("cp.async.commit_group;" ::: "memory")
#define CP_WAIT1()  asm volatile("cp.async.wait_group 1;" ::: "memory")

// ---------------- bf16 GEMM NT: C = alpha * A @ B^T (+ bias) ----------------
// A: [M,K] lda, B: [N,K] ldb bf16 K-major.
// mode 0: f32 C row-major   mode 1: bf16 C row-major
// mode 2: fused residual + transpose: out[(m>>12)*512 + n][m&4095] = acc + x[...]
__global__ __launch_bounds__(256, 2) void gemm_bf16(const bf16* __restrict__ A,
                                                    const bf16* __restrict__ B,
                                                    const float* __restrict__ bias,
                                                    void* __restrict__ Cv,
                                                    const float* __restrict__ xres,
                                                    int K, int lda, int ldb, int ldc,
                                                    float alpha, int mode,
                                                    size_t sA, size_t sB, size_t sC,
                                                    int sBias) {
    extern __shared__ char dsm[];
    uint32_t smem_base = smem_u32(dsm);

    A += (size_t)blockIdx.z * sA;
    B += (size_t)blockIdx.z * sB;
    if (bias) bias += (size_t)blockIdx.z * sBias;
    int bm = blockIdx.y * TM, bn = blockIdx.x * TN;
    int tid = threadIdx.x, wid = tid >> 5, lane = tid & 31;
    int wm = (wid & 1) * 64, wn = (wid >> 1) * 32;

    // cooperative load: 2 threads per 128B row; XOR swizzle granule ^= row&7
    int lrow = tid >> 1;
    int g0 = (tid & 1) * 4;
    const bf16* ag = A + (size_t)(bm + lrow) * lda + g0 * 8;
    const bf16* bg = B + (size_t)(bn + lrow) * ldb + g0 * 8;
    int rx = lrow & 7;
    uint32_t sAoff[4], sBoff[4];
    #pragma unroll
    for (int j = 0; j < 4; j++) {
        uint32_t o = (uint32_t)lrow * 128 + (uint32_t)(((g0 + j) ^ rx) << 4);
        sAoff[j] = o;
        sBoff[j] = TILE_BYTES + o;
    }

    // ldmatrix lane addressing (tile-relative byte offsets)
    int arl = (lane & 7) + ((lane >> 3) & 1) * 8;
    int ahi = lane >> 4;
    uint32_t a_rowoff[4]; int a_rx[4];
    #pragma unroll
    for (int mf = 0; mf < 4; mf++) {
        int row = wm + mf * 16 + arl;
        a_rowoff[mf] = (uint32_t)row * 128;
        a_rx[mf] = row & 7;
    }
    int brl = (lane & 7) + ((lane >> 4) & 1) * 8;
    int bhi = (lane >> 3) & 1;
    uint32_t b_rowoff[2]; int b_rx[2];
    #pragma unroll
    for (int ng = 0; ng < 2; ng++) {
        int row = wn + ng * 16 + brl;
        b_rowoff[ng] = TILE_BYTES + (uint32_t)row * 128;
        b_rx[ng] = row & 7;
    }

    const int NC = K / BK;

    // prologue: stages 0,1
    #pragma unroll
    for (int c = 0; c < 2; c++) {
        uint32_t st = smem_base + c * STG_BYTES;
        const bf16* a0 = ag + c * BK;
        const bf16* b0 = bg + c * BK;
        #pragma unroll
        for (int j = 0; j < 4; j++) cp16(st + sAoff[j], a0 + j * 8);
        #pragma unroll
        for (int j = 0; j < 4; j++) cp16(st + sBoff[j], b0 + j * 8);
        CP_COMMIT();
    }

    float acc[4][4][4];
    #pragma unroll
    for (int i = 0; i < 4; i++)
        #pragma unroll
        for (int j = 0; j < 4; j++)
            #pragma unroll
            for (int r = 0; r < 4; r++) acc[i][j][r] = 0.f;

    for (int c = 0; c < NC; c++) {
        int buf = c % NSTAGE;
        CP_WAIT1();
        __syncthreads();
        // prefetch stage c+2 (single barrier: all warps finished iter c-1 MMAs)
        if (c + 2 < NC) {
            uint32_t st = smem_base + ((c + 2) % NSTAGE) * STG_BYTES;
            const bf16* a0 = ag + (c + 2) * BK;
            const bf16* b0 = bg + (c + 2) * BK;
            #pragma unroll
            for (int j = 0; j < 4; j++) cp16(st + sAoff[j], a0 + j * 8);
            #pragma unroll
            for (int j = 0; j < 4; j++) cp16(st + sBoff[j], b0 + j * 8);
        }
        CP_COMMIT();

        uint32_t base = smem_base + buf * STG_BYTES;
        #pragma unroll
        for (int kf = 0; kf < 4; kf++) {
            uint32_t a[4][4], b[2][4];
            #pragma unroll
            for (int mf = 0; mf < 4; mf++)
                ldsm4(a[mf], base + a_rowoff[mf] +
                      (uint32_t)(((((kf << 1) | ahi)) ^ a_rx[mf]) << 4));
            #pragma unroll
            for (int ng = 0; ng < 2; ng++)
                ldsm4(b[ng], base + b_rowoff[ng] +
                      (uint32_t)(((((kf << 1) | bhi)) ^ b_rx[ng]) << 4));
            #pragma unroll
            for (int mf = 0; mf < 4; mf++)
                #pragma unroll
                for (int ng = 0; ng < 2; ng++) {
                    mma_bf16(acc[mf][ng * 2 + 0], a[mf], b[ng][0], b[ng][1]);
                    mma_bf16(acc[mf][ng * 2 + 1], a[mf], b[ng][2], b[ng][3]);
                }
        }
    }
    __syncthreads();

    // epilogue
    int r4 = lane >> 2, c2 = (lane & 3) * 2;
    #pragma unroll
    for (int mf = 0; mf < 4; mf++) {
        int m0 = bm + wm + mf * 16 + r4;
        #pragma unroll
        for (int nf = 0; nf < 4; nf++) {
            int n0 = bn + wn + (nf >> 1) * 16 + (nf & 1) * 8 + c2;
            float bx = 0.f, by = 0.f;
            if (bias) { bx = bias[n0]; by = bias[n0 + 1]; }
            float* ac = acc[mf][nf];
            float x0 = ac[0] * alpha + bx, y0 = ac[1] * alpha + by;
            float x1 = ac[2] * alpha + bx, y1 = ac[3] * alpha + by;
            if (mode == 1) {
                bf16* C = (bf16*)Cv + blockIdx.z * sC;
                bf162 h0 = __floats2bfloat162_rn(x0, y0);
                bf162 h1 = __floats2bfloat162_rn(x1, y1);
                *(bf162*)(C + (size_t)m0 * ldc + n0) = h0;
                *(bf162*)(C + (size_t)(m0 + 8) * ldc + n0) = h1;
            } else if (mode == 0) {
                float* C = (float*)Cv + blockIdx.z * sC;
                *(float2*)(C + (size_t)m0 * ldc + n0) = make_float2(x0, y0);
                *(float2*)(C + (size_t)(m0 + 8) * ldc + n0) = make_float2(x1, y1);
            } else {
                // fused residual + transpose to [B, C, H, W]
                float* C = (float*)Cv;
                int m1 = m0 + 8;
                size_t i00 = (((size_t)(m0 >> 12) * CDIM) + n0) * HWDIM + (m0 & 4095);
                size_t i01 = (((size_t)(m0 >> 12) * CDIM) + n0 + 1) * HWDIM + (m0 & 4095);
                size_t i10 = (((size_t)(m1 >> 12) * CDIM) + n0) * HWDIM + (m1 & 4095);
                size_t i11 = (((size_t)(m1 >> 12) * CDIM) + n0 + 1) * HWDIM + (m1 & 4095);
                C[i00] = x0 + xres[i00];
                C[i01] = y0 + xres[i01];
                C[i10] = x1 + xres[i10];
                C[i11] = y1 + xres[i11];
            }
        }
    }
}

// ---------------- weight f32 -> bf16 + bias packing --------------------------
__global__ __launch_bounds__(256) void convert_w(const float* __restrict__ W0,
                                                 const float* __restrict__ W1,
                                                 const float* __restrict__ W2,
                                                 const float* __restrict__ W3,
                                                 bf16* __restrict__ out,
                                                 const float* __restrict__ b0,
                                                 const float* __restrict__ b1,
                                                 const float* __restrict__ b2,
                                                 float* __restrict__ bp) {
    int i = blockIdx.x * 256 + threadIdx.x;
    const int WN = CDIM * CDIM;
    int sel = i / WN, r = i % WN;
    const float* W = (sel == 0) ? W0 : (sel == 1) ? W1 : (sel == 2) ? W2 : W3;
    out[i] = __float2bfloat16(W[r]);
    if (i < 3 * CDIM) {
        int bs = i / CDIM, br = i % CDIM;
        const float* b = (bs == 0) ? b0 : (bs == 1) ? b1 : b2;
        bp[i] = b[br];
    }
}

// ---------------- GroupNorm -> bf16 [B,N,C] --------------------------------
__global__ __launch_bounds__(256) void gn_kernel(const float* __restrict__ x,
                                                 const float* __restrict__ gamma,
                                                 const float* __restrict__ beta,
                                                 bf16* __restrict__ xn) {
    int b = blockIdx.x >> 5;
    int g = blockIdx.x & 31;
    const float* xp = x + ((size_t)b * CDIM + (size_t)g * CPG) * HWDIM;
    const int NEL = CPG * HWDIM;

    float s = 0.f, s2 = 0.f;
    for (int i = threadIdx.x; i < NEL; i += 256) {
        float v = xp[i];
        s += v; s2 += v * v;
    }
    __shared__ float rs[256], rs2[256];
    rs[threadIdx.x] = s; rs2[threadIdx.x] = s2;
    __syncthreads();
    for (int st = 128; st > 0; st >>= 1) {
        if (threadIdx.x < st) { rs[threadIdx.x] += rs[threadIdx.x + st];
                                rs2[threadIdx.x] += rs2[threadIdx.x + st]; }
        __syncthreads();
    }
    float mean = rs[0] * (1.f / NEL);
    float var  = rs2[0] * (1.f / NEL) - mean * mean;
    float rstd = rsqrtf(var + EPSV);

    for (int i = threadIdx.x; i < NEL; i += 256) {
        int c  = i & (CPG - 1);
        int hw = i >> 4;
        int cg = g * CPG + c;
        float v = xp[(size_t)c * HWDIM + hw];
        xn[((size_t)b * HWDIM + hw) * CDIM + cg] =
            __float2bfloat16((v - mean) * rstd * gamma[cg] + beta[cg]);
    }
}

// ---------------- Transpose V (bf16): [B,N,C] -> [B,C,N] --------------------
__global__ __launch_bounds__(256) void transpose_vt(const bf16* __restrict__ V,
                                                    bf16* __restrict__ Vt) {
    __shared__ bf16 t[32][34];
    int b  = blockIdx.z;
    int n0 = blockIdx.x * 32;
    int c0 = blockIdx.y * 32;
    int tx = threadIdx.x & 31, ty = threadIdx.x >> 5;
    const size_t str = (size_t)HWDIM * CDIM;
    #pragma unroll
    for (int i = 0; i < 4; i++)
        t[ty + i * 8][tx] = V[b * str + (size_t)(n0 + ty + i * 8) * CDIM + c0 + tx];
    __syncthreads();
    #pragma unroll
    for (int i = 0; i < 4; i++)
        Vt[b * str + (size_t)(c0 + ty + i * 8) * HWDIM + n0 + tx] = t[tx][ty + i * 8];
}

// ---------------- Softmax: bf16 S row -> bf16 P row, f32 internal -----------
__global__ __launch_bounds__(256) void softmax_kernel(const bf16* __restrict__ S,
                                                      bf16* __restrict__ P) {
    __shared__ float red[256];
    const bf16* g = S + (size_t)blockIdx.x * HWDIM;
    bf16* p = P + (size_t)blockIdx.x * HWDIM;
    int tid = threadIdx.x;

    float vals[16];
    float m = -1e30f;
    #pragma unroll
    for (int i = 0; i < 2; i++) {
        uint4 pk = *(const uint4*)(g + tid * 16 + i * 8);  // 8 bf16
        const uint32_t* w = &pk.x;
        #pragma unroll
        for (int j = 0; j < 4; j++) {
            bf162 h = *(const bf162*)&w[j];
            float lo = __bfloat162float(h.x), hi = __bfloat162float(h.y);
            vals[i * 8 + j * 2] = lo; vals[i * 8 + j * 2 + 1] = hi;
            m = fmaxf(m, fmaxf(lo, hi));
        }
    }
    red[tid] = m; __syncthreads();
    for (int st = 128; st > 0; st >>= 1) {
        if (tid < st) red[tid] = fmaxf(red[tid], red[tid + st]);
        __syncthreads();
    }
    m = red[0];
    __syncthreads();

    float sum = 0.f;
    #pragma unroll
    for (int i = 0; i < 16; i++) {
        vals[i] = __expf(vals[i] - m);
        sum += vals[i];
    }
    red[tid] = sum; __syncthreads();
    for (int st = 128; st > 0; st >>= 1) {
        if (tid < st) red[tid] += red[tid + st];
        __syncthreads();
    }
    float inv = 1.f / red[0];

    #pragma unroll
    for (int i = 0; i < 2; i++) {
        uint4 pk;
        uint32_t* w = &pk.x;
        #pragma unroll
        for (int j = 0; j < 4; j++) {
            bf162 h = __floats2bfloat162_rn(vals[i * 8 + j * 2] * inv,
                                            vals[i * 8 + j * 2 + 1] * inv);
            w[j] = *(uint32_t*)&h;
        }
        *(uint4*)(p + tid * 16 + i * 8) = pk;
    }
}

// ---------------- launch ----------------------------------------------------
extern "C" void kernel_launch(void* const* d_in, const int* in_sizes, int n_in,
                              void* d_out, int out_size) {
    const float* x     = (const float*)d_in[0];
    const float* gamma = (const float*)d_in[1];
    const float* beta  = (const float*)d_in[2];
    const float* Wq    = (const float*)d_in[3];
    const float* bq    = (const float*)d_in[4];
    const float* Wk    = (const float*)d_in[5];
    const float* bk    = (const float*)d_in[6];
    const float* Wv    = (const float*)d_in[7];
    const float* bv    = (const float*)d_in[8];
    const float* Wo    = (const float*)d_in[9];
    float* out = (float*)d_out;

    bf16 *xnb, *qkv, *vtb, *sb, *pb, *attnb, *wb;
    float *biasp;
    cudaGetSymbolAddress((void**)&xnb,   g_xnb);
    cudaGetSymbolAddress((void**)&qkv,   g_qkv);
    cudaGetSymbolAddress((void**)&vtb,   g_vtb);
    cudaGetSymbolAddress((void**)&sb,    g_sb);
    cudaGetSymbolAddress((void**)&pb,    g_pb);
    cudaGetSymbolAddress((void**)&attnb, g_attnb);
    cudaGetSymbolAddress((void**)&wb,    g_wb);
    cudaGetSymbolAddress((void**)&biasp, g_biasp);

    static bool attr_set = false;
    if (!attr_set) {
        cudaFuncSetAttribute(gemm_bf16, cudaFuncAttributeMaxDynamicSharedMemorySize, SMEM_DYN);
        attr_set = true;
    }

    const int M_all = BATCH * HWDIM;
    const size_t strQ = (size_t)HWDIM * CDIM;
    const size_t strS = (size_t)HWDIM * HWDIM;
    const size_t strP = (size_t)M_all * CDIM;   // stride between Q,K,V planes
    const int WN = CDIM * CDIM;
    const float inv_sqrt_c = 0.044194173824159216f;

    bf16* qb = qkv;
    bf16* kb = qkv + strP;
    bf16* vb = qkv + 2 * strP;
    bf16* wob = wb + 3 * WN;

    // 0. weights -> bf16, biases packed (one launch)
    convert_w<<<4 * WN / 256, 256>>>(Wq, Wk, Wv, Wo, wb, bq, bk, bv, biasp);

    // 1. GroupNorm -> bf16 [B,N,C]
    gn_kernel<<<BATCH * 32, 256>>>(x, gamma, beta, xnb);

    // 2. Q/K/V projections in ONE launch (z selects weight/bias/output plane)
    dim3 gqkv(CDIM / TN, M_all / TM, 3);
    gemm_bf16<<<gqkv, 256, SMEM_DYN>>>(xnb, wb, biasp, qkv, nullptr,
                                       CDIM, CDIM, CDIM, CDIM, 1.f, 1,
                                       0, (size_t)WN, strP, CDIM);

    // 3. V^T
    dim3 gtr(HWDIM / 32, CDIM / 32, BATCH);
    transpose_vt<<<gtr, 256>>>(vb, vtb);

    // 4. S = (Q @ K^T) / sqrt(C)  (bf16 out)
    dim3 gs(HWDIM / TN, HWDIM / TM, BATCH);
    gemm_bf16<<<gs, 256, SMEM_DYN>>>(qb, kb, nullptr, sb, nullptr,
                                     CDIM, CDIM, CDIM, HWDIM,
                                     inv_sqrt_c, 1, strQ, strQ, strS, 0);

    // 5. softmax -> bf16 P
    softmax_kernel<<<M_all, 256>>>(sb, pb);

    // 6. A = P @ Vt^T  (bf16 out)
    dim3 gpv(CDIM / TN, HWDIM / TM, BATCH);
    gemm_bf16<<<gpv, 256, SMEM_DYN>>>(pb, vtb, nullptr, attnb, nullptr,
                                      HWDIM, HWDIM, HWDIM, CDIM,
                                      1.f, 1, strS, strQ, strQ, 0);

    // 7. O = A @ Wo^T fused with residual + transpose to [B,C,H,W]
    dim3 gproj(CDIM / TN, M_all / TM, 1);
    gemm_bf16<<<gproj, 256, SMEM_DYN>>>(attnb, wob, nullptr, out, x,
                                        CDIM, CDIM, CDIM, CDIM, 1.f, 2, 0, 0, 0, 0);
}

// round 9
// speedup vs baseline: 1.3655x; 1.0015x over previous
#include <cuda_runtime.h>
#include <cuda_bf16.h>
#include <math.h>
#include <stdint.h>

// Shapes (fixed)
#define BATCH 8
#define CDIM 512
#define HWDIM 4096
#define CPG 16
#define EPSV 1e-6f

// GEMM tiling: 128x128 CTA tile, 128B smem rows, 3-stage cp.async
#define TM 128
#define TN 128
#define BK 64                           // bf16 elements per chunk (128B)
#define BK8 128                         // fp8 elements per chunk (128B)
#define TILE_BYTES (TM * 128)           // 16KB per operand stage
#define STG_BYTES (2 * TILE_BYTES)      // 32KB
#define NSTAGE 3
#define SMEM_DYN (NSTAGE * STG_BYTES)   // 96KB

typedef __nv_bfloat16 bf16;
typedef __nv_bfloat162 bf162;

// ---------------- scratch (device globals) ---------------------------------
__device__ bf16    g_xnb [(size_t)BATCH * HWDIM * CDIM];     // 32MB GN out [B,N,C]
__device__ uint8_t g_qk8 [(size_t)2 * BATCH * HWDIM * CDIM]; // 32MB Q,K fp8
__device__ bf16    g_vb  [(size_t)BATCH * HWDIM * CDIM];     // 32MB V bf16
__device__ bf16    g_vtb [(size_t)BATCH * HWDIM * CDIM];     // 32MB V^T [B,C,N]
__device__ bf16    g_sb  [(size_t)BATCH * HWDIM * HWDIM];    // 256MB scores bf16
__device__ bf16    g_pb  [(size_t)BATCH * HWDIM * HWDIM];    // 256MB softmax(P)
__device__ bf16    g_attnb[(size_t)BATCH * HWDIM * CDIM];    // 32MB P@V out
__device__ bf16    g_wb  [4 * CDIM * CDIM];                  // 2MB bf16 weights
__device__ float   g_biasp[3 * CDIM];                        // packed biases

// ---------------- PTX helpers ----------------------------------------------
__device__ __forceinline__ uint32_t smem_u32(const void* p) {
    uint32_t a;
    asm("{ .reg .u64 t; cvta.to.shared.u64 t, %1; cvt.u32.u64 %0, t; }"
        : "=r"(a) : "l"(p));
    return a;
}

__device__ __forceinline__ void ldsm4(uint32_t* r, uint32_t addr) {
    asm volatile("ldmatrix.sync.aligned.m8n8.x4.shared.b16 {%0,%1,%2,%3}, [%4];"
                 : "=r"(r[0]), "=r"(r[1]), "=r"(r[2]), "=r"(r[3]) : "r"(addr));
}

__device__ __forceinline__ void mma_bf16(float* c, const uint32_t* a,
                                         uint32_t b0, uint32_t b1) {
    asm volatile(
        "mma.sync.aligned.m16n8k16.row.col.f32.bf16.bf16.f32 "
        "{%0,%1,%2,%3}, {%4,%5,%6,%7}, {%8,%9}, {%0,%1,%2,%3};"
        : "+f"(c[0]), "+f"(c[1]), "+f"(c[2]), "+f"(c[3])
        : "r"(a[0]), "r"(a[1]), "r"(a[2]), "r"(a[3]), "r"(b0), "r"(b1));
}

__device__ __forceinline__ void mma_fp8(float* c, const uint32_t* a,
                                        uint32_t b0, uint32_t b1) {
    asm volatile(
        "mma.sync.aligned.m16n8k32.row.col.f32.e4m3.e4m3.f32 "
        "{%0,%1,%2,%3}, {%4,%5,%6,%7}, {%8,%9}, {%0,%1,%2,%3};"
        : "+f"(c[0]), "+f"(c[1]), "+f"(c[2]), "+f"(c[3])
        : "r"(a[0]), "r"(a[1]), "r"(a[2]), "r"(a[3]), "r"(b0), "r"(b1));
}

// packs (lo, hi) -> fp8x2, lo in low byte
__device__ __forceinline__ uint16_t pack_e4m3(float lo, float hi) {
    uint16_t r;
    asm("cvt.rn.satfinite.e4m3x2.f32 %0, %1, %2;" : "=h"(r) : "f"(hi), "f"(lo));
    return r;
}

__device__ __forceinline__ void cp16(uint32_t dst, const void* src) {
    asm volatile("cp.async.cg.shared.global [%0], [%1], 16;" :: "r"(dst), "l"(src));
}
#define CP_COMMIT() asm volatile("cp.async.commit_group;" ::: "memory")
#define CP_WAIT1()  asm volatile("cp.async.wait_group 1;" ::: "memory")

// ---------------- bf16 GEMM NT: C = alpha * A @ B^T (+ bias) ----------------
// mode 0: f32 C   mode 1: bf16 C   mode 2: fused residual+transpose f32 out
// mode 4: QKV: blockIdx.z<2 -> fp8 C (plane z of Cv); z==2 -> bf16 to Cv2
__global__ __launch_bounds__(256, 2) void gemm_bf16(const bf16* __restrict__ A,
                                                    const bf16* __restrict__ B,
                                                    const float* __restrict__ bias,
                                                    void* __restrict__ Cv,
                                                    void* __restrict__ Cv2,
                                                    const float* __restrict__ xres,
                                                    int K, int lda, int ldb, int ldc,
                                                    float alpha, int mode,
                                                    size_t sA, size_t sB, size_t sC,
                                                    int sBias) {
    extern __shared__ char dsm[];
    uint32_t smem_base = smem_u32(dsm);

    A += (size_t)blockIdx.z * sA;
    B += (size_t)blockIdx.z * sB;
    if (bias) bias += (size_t)blockIdx.z * sBias;
    int bm = blockIdx.y * TM, bn = blockIdx.x * TN;
    int tid = threadIdx.x, wid = tid >> 5, lane = tid & 31;
    int wm = (wid & 1) * 64, wn = (wid >> 1) * 32;

    int lrow = tid >> 1;
    int g0 = (tid & 1) * 4;
    const bf16* ag = A + (size_t)(bm + lrow) * lda + g0 * 8;
    const bf16* bg = B + (size_t)(bn + lrow) * ldb + g0 * 8;
    int rx = lrow & 7;
    uint32_t sAoff[4], sBoff[4];
    #pragma unroll
    for (int j = 0; j < 4; j++) {
        uint32_t o = (uint32_t)lrow * 128 + (uint32_t)(((g0 + j) ^ rx) << 4);
        sAoff[j] = o;
        sBoff[j] = TILE_BYTES + o;
    }

    int arl = (lane & 7) + ((lane >> 3) & 1) * 8;
    int ahi = lane >> 4;
    uint32_t a_rowoff[4]; int a_rx[4];
    #pragma unroll
    for (int mf = 0; mf < 4; mf++) {
        int row = wm + mf * 16 + arl;
        a_rowoff[mf] = (uint32_t)row * 128;
        a_rx[mf] = row & 7;
    }
    int brl = (lane & 7) + ((lane >> 4) & 1) * 8;
    int bhi = (lane >> 3) & 1;
    uint32_t b_rowoff[2]; int b_rx[2];
    #pragma unroll
    for (int ng = 0; ng < 2; ng++) {
        int row = wn + ng * 16 + brl;
        b_rowoff[ng] = TILE_BYTES + (uint32_t)row * 128;
        b_rx[ng] = row & 7;
    }

    const int NC = K / BK;

    #pragma unroll
    for (int c = 0; c < 2; c++) {
        uint32_t st = smem_base + c * STG_BYTES;
        const bf16* a0 = ag + c * BK;
        const bf16* b0 = bg + c * BK;
        #pragma unroll
        for (int j = 0; j < 4; j++) cp16(st + sAoff[j], a0 + j * 8);
        #pragma unroll
        for (int j = 0; j < 4; j++) cp16(st + sBoff[j], b0 + j * 8);
        CP_COMMIT();
    }

    float acc[4][4][4];
    #pragma unroll
    for (int i = 0; i < 4; i++)
        #pragma unroll
        for (int j = 0; j < 4; j++)
            #pragma unroll
            for (int r = 0; r < 4; r++) acc[i][j][r] = 0.f;

    for (int c = 0; c < NC; c++) {
        int buf = c % NSTAGE;
        CP_WAIT1();
        __syncthreads();
        if (c + 2 < NC) {
            uint32_t st = smem_base + ((c + 2) % NSTAGE) * STG_BYTES;
            const bf16* a0 = ag + (c + 2) * BK;
            const bf16* b0 = bg + (c + 2) * BK;
            #pragma unroll
            for (int j = 0; j < 4; j++) cp16(st + sAoff[j], a0 + j * 8);
            #pragma unroll
            for (int j = 0; j < 4; j++) cp16(st + sBoff[j], b0 + j * 8);
        }
        CP_COMMIT();

        uint32_t base = smem_base + buf * STG_BYTES;
        #pragma unroll
        for (int kf = 0; kf < 4; kf++) {
            uint32_t a[4][4], b[2][4];
            #pragma unroll
            for (int mf = 0; mf < 4; mf++)
                ldsm4(a[mf], base + a_rowoff[mf] +
                      (uint32_t)(((((kf << 1) | ahi)) ^ a_rx[mf]) << 4));
            #pragma unroll
            for (int ng = 0; ng < 2; ng++)
                ldsm4(b[ng], base + b_rowoff[ng] +
                      (uint32_t)(((((kf << 1) | bhi)) ^ b_rx[ng]) << 4));
            #pragma unroll
            for (int mf = 0; mf < 4; mf++)
                #pragma unroll
                for (int ng = 0; ng < 2; ng++) {
                    mma_bf16(acc[mf][ng * 2 + 0], a[mf], b[ng][0], b[ng][1]);
                    mma_bf16(acc[mf][ng * 2 + 1], a[mf], b[ng][2], b[ng][3]);
                }
        }
    }
    __syncthreads();

    // epilogue
    int r4 = lane >> 2, c2 = (lane & 3) * 2;
    #pragma unroll
    for (int mf = 0; mf < 4; mf++) {
        int m0 = bm + wm + mf * 16 + r4;
        #pragma unroll
        for (int nf = 0; nf < 4; nf++) {
            int n0 = bn + wn + (nf >> 1) * 16 + (nf & 1) * 8 + c2;
            float bx = 0.f, by = 0.f;
            if (bias) { bx = bias[n0]; by = bias[n0 + 1]; }
            float* ac = acc[mf][nf];
            float x0 = ac[0] * alpha + bx, y0 = ac[1] * alpha + by;
            float x1 = ac[2] * alpha + bx, y1 = ac[3] * alpha + by;
            if (mode == 1) {
                bf16* C = (bf16*)Cv + blockIdx.z * sC;
                bf162 h0 = __floats2bfloat162_rn(x0, y0);
                bf162 h1 = __floats2bfloat162_rn(x1, y1);
                *(bf162*)(C + (size_t)m0 * ldc + n0) = h0;
                *(bf162*)(C + (size_t)(m0 + 8) * ldc + n0) = h1;
            } else if (mode == 0) {
                float* C = (float*)Cv + blockIdx.z * sC;
                *(float2*)(C + (size_t)m0 * ldc + n0) = make_float2(x0, y0);
                *(float2*)(C + (size_t)(m0 + 8) * ldc + n0) = make_float2(x1, y1);
            } else if (mode == 2) {
                // fused residual + transpose to [B, C, H, W]
                float* C = (float*)Cv;
                int m1 = m0 + 8;
                size_t i00 = (((size_t)(m0 >> 12) * CDIM) + n0) * HWDIM + (m0 & 4095);
                size_t i01 = (((size_t)(m0 >> 12) * CDIM) + n0 + 1) * HWDIM + (m0 & 4095);
                size_t i10 = (((size_t)(m1 >> 12) * CDIM) + n0) * HWDIM + (m1 & 4095);
                size_t i11 = (((size_t)(m1 >> 12) * CDIM) + n0 + 1) * HWDIM + (m1 & 4095);
                C[i00] = x0 + xres[i00];
                C[i01] = y0 + xres[i01];
                C[i10] = x1 + xres[i10];
                C[i11] = y1 + xres[i11];
            } else {
                // mode 4: QKV. z<2 -> fp8 plane; z==2 -> bf16 V
                if (blockIdx.z < 2) {
                    uint8_t* C = (uint8_t*)Cv + blockIdx.z * sC;
                    *(uint16_t*)(C + (size_t)m0 * ldc + n0) = pack_e4m3(x0, y0);
                    *(uint16_t*)(C + (size_t)(m0 + 8) * ldc + n0) = pack_e4m3(x1, y1);
                } else {
                    bf16* C = (bf16*)Cv2;
                    bf162 h0 = __floats2bfloat162_rn(x0, y0);
                    bf162 h1 = __floats2bfloat162_rn(x1, y1);
                    *(bf162*)(C + (size_t)m0 * ldc + n0) = h0;
                    *(bf162*)(C + (size_t)(m0 + 8) * ldc + n0) = h1;
                }
            }
        }
    }
}

// ---------------- fp8 S-GEMM NT: S = alpha * Q @ K^T, bf16 out --------------
// A, B: [4096, 512] e4m3, K-major. Per-batch planes via blockIdx.z.
__global__ __launch_bounds__(256, 2) void gemm_s8(const uint8_t* __restrict__ A,
                                                  const uint8_t* __restrict__ B,
                                                  bf16* __restrict__ C,
                                                  int K, int lda, int ldb, int ldc,
                                                  float alpha,
                                                  size_t sA, size_t sB, size_t sC) {
    extern __shared__ char dsm[];
    uint32_t smem_base = smem_u32(dsm);

    A += (size_t)blockIdx.z * sA;
    B += (size_t)blockIdx.z * sB;
    C += (size_t)blockIdx.z * sC;
    int bm = blockIdx.y * TM, bn = blockIdx.x * TN;
    int tid = threadIdx.x, wid = tid >> 5, lane = tid & 31;
    int wm = (wid & 1) * 64, wn = (wid >> 1) * 32;

    // cooperative load: 2 threads per 128B row (BK8=128 fp8 = 128B)
    int lrow = tid >> 1;
    int g0 = (tid & 1) * 4;
    const uint8_t* ag = A + (size_t)(bm + lrow) * lda + g0 * 16;
    const uint8_t* bg = B + (size_t)(bn + lrow) * ldb + g0 * 16;
    int rx = lrow & 7;
    uint32_t sAoff[4], sBoff[4];
    #pragma unroll
    for (int j = 0; j < 4; j++) {
        uint32_t o = (uint32_t)lrow * 128 + (uint32_t)(((g0 + j) ^ rx) << 4);
        sAoff[j] = o;
        sBoff[j] = TILE_BYTES + o;
    }

    // ldmatrix addressing: identical byte layout to bf16 kernel (b16 view)
    int arl = (lane & 7) + ((lane >> 3) & 1) * 8;
    int ahi = lane >> 4;
    uint32_t a_rowoff[4]; int a_rx[4];
    #pragma unroll
    for (int mf = 0; mf < 4; mf++) {
        int row = wm + mf * 16 + arl;
        a_rowoff[mf] = (uint32_t)row * 128;
        a_rx[mf] = row & 7;
    }
    int brl = (lane & 7) + ((lane >> 4) & 1) * 8;
    int bhi = (lane >> 3) & 1;
    uint32_t b_rowoff[2]; int b_rx[2];
    #pragma unroll
    for (int ng = 0; ng < 2; ng++) {
        int row = wn + ng * 16 + brl;
        b_rowoff[ng] = TILE_BYTES + (uint32_t)row * 128;
        b_rx[ng] = row & 7;
    }

    const int NC = K / BK8;   // 512/128 = 4

    #pragma unroll
    for (int c = 0; c < 2; c++) {
        uint32_t st = smem_base + c * STG_BYTES;
        const uint8_t* a0 = ag + c * BK8;
        const uint8_t* b0 = bg + c * BK8;
        #pragma unroll
        for (int j = 0; j < 4; j++) cp16(st + sAoff[j], a0 + j * 16);
        #pragma unroll
        for (int j = 0; j < 4; j++) cp16(st + sBoff[j], b0 + j * 16);
        CP_COMMIT();
    }

    float acc[4][4][4];
    #pragma unroll
    for (int i = 0; i < 4; i++)
        #pragma unroll
        for (int j = 0; j < 4; j++)
            #pragma unroll
            for (int r = 0; r < 4; r++) acc[i][j][r] = 0.f;

    for (int c = 0; c < NC; c++) {
        int buf = c % NSTAGE;
        CP_WAIT1();
        __syncthreads();
        if (c + 2 < NC) {
            uint32_t st = smem_base + ((c + 2) % NSTAGE) * STG_BYTES;
            const uint8_t* a0 = ag + (c + 2) * BK8;
            const uint8_t* b0 = bg + (c + 2) * BK8;
            #pragma unroll
            for (int j = 0; j < 4; j++) cp16(st + sAoff[j], a0 + j * 16);
            #pragma unroll
            for (int j = 0; j < 4; j++) cp16(st + sBoff[j], b0 + j * 16);
        }
        CP_COMMIT();

        uint32_t base = smem_base + buf * STG_BYTES;
        #pragma unroll
        for (int kf = 0; kf < 4; kf++) {   // each kf = 32 fp8 of k
            uint32_t a[4][4], b[2][4];
            #pragma unroll
            for (int mf = 0; mf < 4; mf++)
                ldsm4(a[mf], base + a_rowoff[mf] +
                      (uint32_t)(((((kf << 1) | ahi)) ^ a_rx[mf]) << 4));
            #pragma unroll
            for (int ng = 0; ng < 2; ng++)
                ldsm4(b[ng], base + b_rowoff[ng] +
                      (uint32_t)(((((kf << 1) | bhi)) ^ b_rx[ng]) << 4));
            #pragma unroll
            for (int mf = 0; mf < 4; mf++)
                #pragma unroll
                for (int ng = 0; ng < 2; ng++) {
                    mma_fp8(acc[mf][ng * 2 + 0], a[mf], b[ng][0], b[ng][1]);
                    mma_fp8(acc[mf][ng * 2 + 1], a[mf], b[ng][2], b[ng][3]);
                }
        }
    }
    __syncthreads();

    int r4 = lane >> 2, c2 = (lane & 3) * 2;
    #pragma unroll
    for (int mf = 0; mf < 4; mf++) {
        int m0 = bm + wm + mf * 16 + r4;
        #pragma unroll
        for (int nf = 0; nf < 4; nf++) {
            int n0 = bn + wn + (nf >> 1) * 16 + (nf & 1) * 8 + c2;
            float* ac = acc[mf][nf];
            bf162 h0 = __floats2bfloat162_rn(ac[0] * alpha, ac[1] * alpha);
            bf162 h1 = __floats2bfloat162_rn(ac[2] * alpha, ac[3] * alpha);
            *(bf162*)(C + (size_t)m0 * ldc + n0) = h0;
            *(bf162*)(C + (size_t)(m0 + 8) * ldc + n0) = h1;
        }
    }
}

// ---------------- weight f32 -> bf16 + bias packing --------------------------
__global__ __launch_bounds__(256) void convert_w(const float* __restrict__ W0,
                                                 const float* __restrict__ W1,
                                                 const float* __restrict__ W2,
                                                 const float* __restrict__ W3,
                                                 bf16* __restrict__ out,
                                                 const float* __restrict__ b0,
                                                 const float* __restrict__ b1,
                                                 const float* __restrict__ b2,
                                                 float* __restrict__ bp) {
    int i = blockIdx.x * 256 + threadIdx.x;
    const int WN = CDIM * CDIM;
    int sel = i / WN, r = i % WN;
    const float* W = (sel == 0) ? W0 : (sel == 1) ? W1 : (sel == 2) ? W2 : W3;
    out[i] = __float2bfloat16(W[r]);
    if (i < 3 * CDIM) {
        int bs = i / CDIM, br = i % CDIM;
        const float* b = (bs == 0) ? b0 : (bs == 1) ? b1 : b2;
        bp[i] = b[br];
    }
}

// ---------------- GroupNorm -> bf16 [B,N,C] --------------------------------
__global__ __launch_bounds__(256) void gn_kernel(const float* __restrict__ x,
                                                 const float* __restrict__ gamma,
                                                 const float* __restrict__ beta,
                                                 bf16* __restrict__ xn) {
    int b = blockIdx.x >> 5;
    int g = blockIdx.x & 31;
    const float* xp = x + ((size_t)b * CDIM + (size_t)g * CPG) * HWDIM;
    const int NEL = CPG * HWDIM;

    float s = 0.f, s2 = 0.f;
    for (int i = threadIdx.x; i < NEL; i += 256) {
        float v = xp[i];
        s += v; s2 += v * v;
    }
    __shared__ float rs[256], rs2[256];
    rs[threadIdx.x] = s; rs2[threadIdx.x] = s2;
    __syncthreads();
    for (int st = 128; st > 0; st >>= 1) {
        if (threadIdx.x < st) { rs[threadIdx.x] += rs[threadIdx.x + st];
                                rs2[threadIdx.x] += rs2[threadIdx.x + st]; }
        __syncthreads();
    }
    float mean = rs[0] * (1.f / NEL);
    float var  = rs2[0] * (1.f / NEL) - mean * mean;
    float rstd = rsqrtf(var + EPSV);

    for (int i = threadIdx.x; i < NEL; i += 256) {
        int c  = i & (CPG - 1);
        int hw = i >> 4;
        int cg = g * CPG + c;
        float v = xp[(size_t)c * HWDIM + hw];
        xn[((size_t)b * HWDIM + hw) * CDIM + cg] =
            __float2bfloat16((v - mean) * rstd * gamma[cg] + beta[cg]);
    }
}

// ---------------- Transpose V (bf16): [B,N,C] -> [B,C,N] --------------------
__global__ __launch_bounds__(256) void transpose_vt(const bf16* __restrict__ V,
                                                    bf16* __restrict__ Vt) {
    __shared__ bf16 t[32][34];
    int b  = blockIdx.z;
    int n0 = blockIdx.x * 32;
    int c0 = blockIdx.y * 32;
    int tx = threadIdx.x & 31, ty = threadIdx.x >> 5;
    const size_t str = (size_t)HWDIM * CDIM;
    #pragma unroll
    for (int i = 0; i < 4; i++)
        t[ty + i * 8][tx] = V[b * str + (size_t)(n0 + ty + i * 8) * CDIM + c0 + tx];
    __syncthreads();
    #pragma unroll
    for (int i = 0; i < 4; i++)
        Vt[b * str + (size_t)(c0 + ty + i * 8) * HWDIM + n0 + tx] = t[tx][ty + i * 8];
}

// ---------------- Softmax: bf16 S row -> bf16 P row, f32 internal -----------
__global__ __launch_bounds__(256) void softmax_kernel(const bf16* __restrict__ S,
                                                      bf16* __restrict__ P) {
    __shared__ float red[256];
    const bf16* g = S + (size_t)blockIdx.x * HWDIM;
    bf16* p = P + (size_t)blockIdx.x * HWDIM;
    int tid = threadIdx.x;

    float vals[16];
    float m = -1e30f;
    #pragma unroll
    for (int i = 0; i < 2; i++) {
        uint4 pk = *(const uint4*)(g + tid * 16 + i * 8);
        const uint32_t* w = &pk.x;
        #pragma unroll
        for (int j = 0; j < 4; j++) {
            bf162 h = *(const bf162*)&w[j];
            float lo = __bfloat162float(h.x), hi = __bfloat162float(h.y);
            vals[i * 8 + j * 2] = lo; vals[i * 8 + j * 2 + 1] = hi;
            m = fmaxf(m, fmaxf(lo, hi));
        }
    }
    red[tid] = m; __syncthreads();
    for (int st = 128; st > 0; st >>= 1) {
        if (tid < st) red[tid] = fmaxf(red[tid], red[tid + st]);
        __syncthreads();
    }
    m = red[0];
    __syncthreads();

    float sum = 0.f;
    #pragma unroll
    for (int i = 0; i < 16; i++) {
        vals[i] = __expf(vals[i] - m);
        sum += vals[i];
    }
    red[tid] = sum; __syncthreads();
    for (int st = 128; st > 0; st >>= 1) {
        if (tid < st) red[tid] += red[tid + st];
        __syncthreads();
    }
    float inv = 1.f / red[0];

    #pragma unroll
    for (int i = 0; i < 2; i++) {
        uint4 pk;
        uint32_t* w = &pk.x;
        #pragma unroll
        for (int j = 0; j < 4; j++) {
            bf162 h = __floats2bfloat162_rn(vals[i * 8 + j * 2] * inv,
                                            vals[i * 8 + j * 2 + 1] * inv);
            w[j] = *(uint32_t*)&h;
        }
        *(uint4*)(p + tid * 16 + i * 8) = pk;
    }
}

// ---------------- launch ----------------------------------------------------
extern "C" void kernel_launch(void* const* d_in, const int* in_sizes, int n_in,
                              void* d_out, int out_size) {
    const float* x     = (const float*)d_in[0];
    const float* gamma = (const float*)d_in[1];
    const float* beta  = (const float*)d_in[2];
    const float* Wq    = (const float*)d_in[3];
    const float* bq    = (const float*)d_in[4];
    const float* Wk    = (const float*)d_in[5];
    const float* bk    = (const float*)d_in[6];
    const float* Wv    = (const float*)d_in[7];
    const float* bv    = (const float*)d_in[8];
    const float* Wo    = (const float*)d_in[9];
    float* out = (float*)d_out;

    bf16 *xnb, *vb, *vtb, *sb, *pb, *attnb, *wb;
    uint8_t *qk8;
    float *biasp;
    cudaGetSymbolAddress((void**)&xnb,   g_xnb);
    cudaGetSymbolAddress((void**)&qk8,   g_qk8);
    cudaGetSymbolAddress((void**)&vb,    g_vb);
    cudaGetSymbolAddress((void**)&vtb,   g_vtb);
    cudaGetSymbolAddress((void**)&sb,    g_sb);
    cudaGetSymbolAddress((void**)&pb,    g_pb);
    cudaGetSymbolAddress((void**)&attnb, g_attnb);
    cudaGetSymbolAddress((void**)&wb,    g_wb);
    cudaGetSymbolAddress((void**)&biasp, g_biasp);

    static bool attr_set = false;
    if (!attr_set) {
        cudaFuncSetAttribute(gemm_bf16, cudaFuncAttributeMaxDynamicSharedMemorySize, SMEM_DYN);
        cudaFuncSetAttribute(gemm_s8,  cudaFuncAttributeMaxDynamicSharedMemorySize, SMEM_DYN);
        attr_set = true;
    }

    const int M_all = BATCH * HWDIM;
    const size_t strQ  = (size_t)HWDIM * CDIM;      // bf16 per-batch plane
    const size_t strS  = (size_t)HWDIM * HWDIM;
    const size_t strP8 = (size_t)M_all * CDIM;      // fp8 Q/K plane (bytes)
    const int WN = CDIM * CDIM;
    const float inv_sqrt_c = 0.044194173824159216f;

    uint8_t* q8 = qk8;
    uint8_t* k8 = qk8 + strP8;
    bf16* wob = wb + 3 * WN;

    // 0. weights -> bf16, biases packed
    convert_w<<<4 * WN / 256, 256>>>(Wq, Wk, Wv, Wo, wb, bq, bk, bv, biasp);

    // 1. GroupNorm -> bf16 [B,N,C]
    gn_kernel<<<BATCH * 32, 256>>>(x, gamma, beta, xnb);

    // 2. Q/K/V projections: Q,K -> fp8 planes, V -> bf16 (one launch)
    dim3 gqkv(CDIM / TN, M_all / TM, 3);
    gemm_bf16<<<gqkv, 256, SMEM_DYN>>>(xnb, wb, biasp, qk8, vb, nullptr,
                                       CDIM, CDIM, CDIM, CDIM, 1.f, 4,
                                       0, (size_t)WN, strP8, CDIM);

    // 3. V^T
    dim3 gtr(HWDIM / 32, CDIM / 32, BATCH);
    transpose_vt<<<gtr, 256>>>(vb, vtb);

    // 4. S = (Q @ K^T) / sqrt(C), fp8 inputs, bf16 out
    dim3 gs(HWDIM / TN, HWDIM / TM, BATCH);
    gemm_s8<<<gs, 256, SMEM_DYN>>>(q8, k8, sb,
                                   CDIM, CDIM, CDIM, HWDIM, inv_sqrt_c,
                                   strQ, strQ, strS);

    // 5. softmax -> bf16 P
    softmax_kernel<<<M_all, 256>>>(sb, pb);

    // 6. A = P @ Vt^T  (bf16)
    dim3 gpv(CDIM / TN, HWDIM / TM, BATCH);
    gemm_bf16<<<gpv, 256, SMEM_DYN>>>(pb, vtb, nullptr, attnb, nullptr, nullptr,
                                      HWDIM, HWDIM, HWDIM, CDIM,
                                      1.f, 1, strS, strQ, strQ, 0);

    // 7. O = A @ Wo^T fused with residual + transpose to [B,C,H,W]
    dim3 gproj(CDIM / TN, M_all / TM, 1);
    gemm_bf16<<<gproj, 256, SMEM_DYN>>>(attnb, wob, nullptr, out, nullptr, x,
                                        CDIM, CDIM, CDIM, CDIM, 1.f, 2, 0, 0, 0, 0);
}